// round 6
// baseline (speedup 1.0000x reference)
#include <cuda_runtime.h>
#include <cstdint>

#define BB   16
#define CC   128
#define HH   28
#define WW   28
#define FF   128
#define KK   1152      // CC*9
#define LL   784       // 28*28
#define LPAD 832       // 13*64
#define FT   64
#define LT   64
#define KC   16
#define NKC  (KK/KC)   // 72
#define NST  3         // pipeline stages

// Scratch (allocation-free rule: __device__ globals)
__device__ __align__(16) float g_Pneg[(size_t)BB * KK * LPAD];  // -patches, zero padded
__device__ __align__(16) float g_Wt2[(size_t)KK * 2 * FF];      // W transposed+duplicated [K][2F]: each w twice

// ---------------- im2col (negated), all threads active ----------------
__global__ void __launch_bounds__(256) im2col_kernel(const float* __restrict__ x) {
    const int lp4 = blockIdx.x * 16 + threadIdx.x;
    const int k   = blockIdx.y * 16 + threadIdx.y;
    const int b   = blockIdx.z;
    const int c  = k / 9;
    const int r  = k - c * 9;
    const int kh = r / 3, kw = r - kh * 3;

    const float* xp = x + ((size_t)(b * CC + c)) * (HH * WW);

    float4 v = make_float4(0.f, 0.f, 0.f, 0.f);
    const int l0 = lp4 * 4;
    if (l0 < LL) {                      // whole float4 in-range or fully pad (LL%4==0)
        const int oh  = lp4 / 7;        // 7 float4 per 28-wide image row
        const int ow0 = (lp4 - oh * 7) * 4;
        const int ih  = oh + kh - 1;
        if (ih >= 0 && ih < HH) {
            const float* row = xp + ih * WW;
            const int iw0 = ow0 + kw - 1;
            float* vv = reinterpret_cast<float*>(&v);
#pragma unroll
            for (int j = 0; j < 4; j++) {
                int iw = iw0 + j;
                if (iw >= 0 && iw < WW) vv[j] = -row[iw];
            }
        }
    }
    *reinterpret_cast<float4*>(&g_Pneg[((size_t)(b * KK + k)) * LPAD + l0]) = v;
}

// ---------------- W transpose + duplicate ----------------
__global__ void wtrans_kernel(const float* __restrict__ Wg) {
    int idx = blockIdx.x * blockDim.x + threadIdx.x;
    if (idx >= FF * KK) return;
    int k = idx % KK, f = idx / KK;
    float w = Wg[f * KK + k];
    *reinterpret_cast<float2*>(&g_Wt2[(size_t)k * (2 * FF) + 2 * f]) = make_float2(w, w);
}

// ---------------- packed f32x2 helpers ----------------
__device__ __forceinline__ unsigned long long add2(unsigned long long a, unsigned long long b) {
    unsigned long long r;
    asm("add.rn.f32x2 %0, %1, %2;" : "=l"(r) : "l"(a), "l"(b));
    return r;
}
__device__ __forceinline__ void unpack2(unsigned long long v, float& lo, float& hi) {
    unsigned int a, b;
    asm("mov.b64 {%0, %1}, %2;" : "=r"(a), "=r"(b) : "l"(v));
    lo = __uint_as_float(a);
    hi = __uint_as_float(b);
}

#define CPA16(s, g) asm volatile("cp.async.cg.shared.global [%0], [%1], 16;\n" :: "r"(s), "l"(g))

// ---------------- main L1-distance kernel ----------------
// 128 threads/CTA, tile 64f x 64l, per-thread 4f x 8l.
// sWd: duplicated W [KC][2*FT]; thread reads chunks {c, c+16} (c = tid&15) -> conflict-free,
//      each LDS.128 yields two packed (w,w) u64 operands (zero pack MOVs).
// sP:  plain [KC][LT]; broadcast reads.
__global__ void __launch_bounds__(128) adder_kernel(float* __restrict__ out) {
    __shared__ __align__(16) float sWd[NST][KC][2 * FT];  // 24 KB
    __shared__ __align__(16) float sP [NST][KC][LT];      // 12 KB

    const int tid = threadIdx.x;
    const int b  = blockIdx.z;
    const int f0 = blockIdx.y * FT;
    const int l0 = blockIdx.x * LT;

    const float* gW = g_Wt2 + 2 * f0;                        // [K][2F] slice
    const float* gP = g_Pneg + (size_t)b * KK * LPAD + l0;   // [K][LPAD] slice

    const uint32_t sW_base = (uint32_t)__cvta_generic_to_shared(&sWd[0][0][0]);
    const uint32_t sP_base = (uint32_t)__cvta_generic_to_shared(&sP[0][0][0]);

    // fill mapping (per stage): W tile 16 rows x 128 floats = 512 float4 -> 4/thread
    //                           P tile 16 rows x  64 floats = 256 float4 -> 2/thread
    const int frow = tid >> 3;           // 0..15
    const int fcw  = (tid & 7) * 4;      // W float4-chunk base 0..28
    const int fcp  = (tid & 7) * 2;      // P float4-chunk base 0..14

    auto fill = [&](int s, int bufi) {
        int k0 = s * KC;
        const float* wr = gW + (size_t)(k0 + frow) * (2 * FF);
        uint32_t wd = sW_base + (uint32_t)(((bufi * KC + frow) * (2 * FT)) * 4);
#pragma unroll
        for (int j = 0; j < 4; j++)
            CPA16(wd + (fcw + j) * 16, wr + (fcw + j) * 4);
        const float* pr = gP + (size_t)(k0 + frow) * LPAD;
        uint32_t pd = sP_base + (uint32_t)(((bufi * KC + frow) * LT) * 4);
#pragma unroll
        for (int j = 0; j < 2; j++)
            CPA16(pd + (fcp + j) * 16, pr + (fcp + j) * 4);
        asm volatile("cp.async.commit_group;\n" ::: "memory");
    };

    const int tc = tid & 15;             // W chunk id: f-pairs {2tc,2tc+1} and {2tc+32,2tc+33}
    const int tl = (tid >> 4) * 8;       // 8 consecutive l (0..56)

    unsigned long long acc[4][4];        // acc[f][lpair]
#pragma unroll
    for (int i = 0; i < 4; i++)
#pragma unroll
        for (int j = 0; j < 4; j++) acc[i][j] = 0ULL;

    const unsigned long long ABSM = 0x7FFFFFFF7FFFFFFFULL;

    fill(0, 0);
    fill(1, 1);
    int buf = 0;
    for (int s = 0; s < NKC; s++) {
        asm volatile("cp.async.wait_group 1;\n" ::: "memory");
        __syncthreads();
        if (s + 2 < NKC) {
            int nbuf = buf + 2; if (nbuf >= NST) nbuf -= NST;
            fill(s + 2, nbuf);
        }
#pragma unroll
        for (int kc = 0; kc < KC; kc++) {
            ulonglong2 wA = *reinterpret_cast<const ulonglong2*>(&sWd[buf][kc][4 * tc]);        // (w0,w0),(w1,w1)
            ulonglong2 wB = *reinterpret_cast<const ulonglong2*>(&sWd[buf][kc][4 * tc + 64]);   // (w2,w2),(w3,w3)
            ulonglong2 pA = *reinterpret_cast<const ulonglong2*>(&sP[buf][kc][tl]);             // (p0,p1),(p2,p3)
            ulonglong2 pB = *reinterpret_cast<const ulonglong2*>(&sP[buf][kc][tl + 4]);         // (p4,p5),(p6,p7)
            unsigned long long w[4] = {wA.x, wA.y, wB.x, wB.y};
            unsigned long long p[4] = {pA.x, pA.y, pB.x, pB.y};
#pragma unroll
            for (int i = 0; i < 4; i++) {
#pragma unroll
                for (int j = 0; j < 4; j++) {
                    unsigned long long d = add2(w[i], p[j]) & ABSM;   // |w - p| packed over l
                    acc[i][j] = add2(acc[i][j], d);
                }
            }
        }
        buf = buf + 1 == NST ? 0 : buf + 1;
    }

    // epilogue: out = -sum. 8 l per f -> two float4 stores. 784 % 8 == 0 -> all-in or all-pad.
    const int lbase = l0 + tl;
    if (lbase < LL) {
        const int fl[4] = {2 * tc, 2 * tc + 1, 2 * tc + 32, 2 * tc + 33};
#pragma unroll
        for (int i = 0; i < 4; i++) {
            float a[8];
            unpack2(acc[i][0], a[0], a[1]);
            unpack2(acc[i][1], a[2], a[3]);
            unpack2(acc[i][2], a[4], a[5]);
            unpack2(acc[i][3], a[6], a[7]);
            float* orow = out + ((size_t)(b * FF + f0 + fl[i])) * LL + lbase;
            *reinterpret_cast<float4*>(orow)     = make_float4(-a[0], -a[1], -a[2], -a[3]);
            *reinterpret_cast<float4*>(orow + 4) = make_float4(-a[4], -a[5], -a[6], -a[7]);
        }
    }
}

extern "C" void kernel_launch(void* const* d_in, const int* in_sizes, int n_in,
                              void* d_out, int out_size) {
    const float* x  = (const float*)d_in[0];   // [16,128,28,28]
    const float* Wg = (const float*)d_in[1];   // [128,128,3,3]
    float* out = (float*)d_out;                // [16,128,28,28]

    dim3 g1(13, 72, 16);
    dim3 b1(16, 16, 1);
    im2col_kernel<<<g1, b1>>>(x);
    wtrans_kernel<<<(FF * KK + 255) / 256, 256>>>(Wg);

    dim3 grid(LPAD / LT /*13*/, FF / FT /*2*/, BB /*16*/);
    adder_kernel<<<grid, 128>>>(out);
}

// round 7
// speedup vs baseline: 1.0104x; 1.0104x over previous
#include <cuda_runtime.h>
#include <cstdint>

#define BB   16
#define CC   128
#define HH   28
#define WW   28
#define FF   128
#define KK   1152      // CC*9
#define LL   784       // 28*28
#define LPAD 832       // 13*64
#define FT   64
#define LT   64
#define KC   16
#define NKC  (KK/KC)   // 72
#define NST  3         // pipeline stages

// Scratch (allocation-free rule: __device__ globals)
__device__ __align__(16) float g_Pneg[(size_t)BB * KK * LPAD];  // -patches, zero padded
__device__ __align__(16) float g_Wt2[(size_t)KK * 2 * FF];      // W transposed+duplicated [K][2F]

// ---------------- im2col (negated) ----------------
__global__ void __launch_bounds__(256) im2col_kernel(const float* __restrict__ x) {
    const int lp4 = blockIdx.x * 16 + threadIdx.x;
    const int k   = blockIdx.y * 16 + threadIdx.y;
    const int b   = blockIdx.z;
    const int c  = k / 9;
    const int r  = k - c * 9;
    const int kh = r / 3, kw = r - kh * 3;

    const float* xp = x + ((size_t)(b * CC + c)) * (HH * WW);

    float4 v = make_float4(0.f, 0.f, 0.f, 0.f);
    const int l0 = lp4 * 4;
    if (l0 < LL) {
        const int oh  = lp4 / 7;
        const int ow0 = (lp4 - oh * 7) * 4;
        const int ih  = oh + kh - 1;
        if (ih >= 0 && ih < HH) {
            const float* row = xp + ih * WW;
            const int iw0 = ow0 + kw - 1;
            float* vv = reinterpret_cast<float*>(&v);
#pragma unroll
            for (int j = 0; j < 4; j++) {
                int iw = iw0 + j;
                if (iw >= 0 && iw < WW) vv[j] = -row[iw];
            }
        }
    }
    *reinterpret_cast<float4*>(&g_Pneg[((size_t)(b * KK + k)) * LPAD + l0]) = v;
}

// ---------------- W transpose + duplicate ----------------
__global__ void wtrans_kernel(const float* __restrict__ Wg) {
    int idx = blockIdx.x * blockDim.x + threadIdx.x;
    if (idx >= FF * KK) return;
    int k = idx % KK, f = idx / KK;
    float w = Wg[f * KK + k];
    *reinterpret_cast<float2*>(&g_Wt2[(size_t)k * (2 * FF) + 2 * f]) = make_float2(w, w);
}

// ---------------- packed f32x2 helpers ----------------
__device__ __forceinline__ unsigned long long add2(unsigned long long a, unsigned long long b) {
    unsigned long long r;
    asm("add.rn.f32x2 %0, %1, %2;" : "=l"(r) : "l"(a), "l"(b));
    return r;
}
__device__ __forceinline__ void unpack2(unsigned long long v, float& lo, float& hi) {
    unsigned int a, b;
    asm("mov.b64 {%0, %1}, %2;" : "=r"(a), "=r"(b) : "l"(v));
    lo = __uint_as_float(a);
    hi = __uint_as_float(b);
}

#define CPA16(s, g) asm volatile("cp.async.cg.shared.global [%0], [%1], 16;\n" :: "r"(s), "l"(g))

// ---------------- main L1-distance kernel ----------------
// 256 threads/CTA, tile 64f x 64l, per-thread 4f x 4l = 16 terms.
// sWd: duplicated W [KC][2*FT]; thread tc=tid&15 reads f-pairs {2tc,2tc+1} at byte 16*tc
//      and {2tc+32,2tc+33} at byte 16*tc+256 -> 16B lane stride, conflict-free, zero pack MOVs.
// sP:  plain [KC][LT]; tl=(tid>>4)*4 -> LDS.128 broadcast.
__global__ void __launch_bounds__(256) adder_kernel(float* __restrict__ out) {
    __shared__ __align__(16) float sWd[NST][KC][2 * FT];  // 24 KB
    __shared__ __align__(16) float sP [NST][KC][LT];      // 12 KB

    const int tid = threadIdx.x;
    const int b  = blockIdx.z;
    const int f0 = blockIdx.y * FT;
    const int l0 = blockIdx.x * LT;

    const float* gW = g_Wt2 + 2 * f0;                        // [K][2F] slice
    const float* gP = g_Pneg + (size_t)b * KK * LPAD + l0;   // [K][LPAD] slice

    const uint32_t sW_base = (uint32_t)__cvta_generic_to_shared(&sWd[0][0][0]);
    const uint32_t sP_base = (uint32_t)__cvta_generic_to_shared(&sP[0][0][0]);

    // fill (per stage): W tile 16 rows x 128 floats = 512 float4 -> 2/thread
    //                   P tile 16 rows x  64 floats = 256 float4 -> 1/thread
    const int frow = tid >> 4;           // 0..15
    const int fcw  = (tid & 15) * 2;     // W float4 chunk base (2 consecutive)
    const int fcp  = (tid & 15);         // P float4 chunk

    auto fill = [&](int s, int bufi) {
        int k0 = s * KC;
        const float* wr = gW + (size_t)(k0 + frow) * (2 * FF);
        uint32_t wd = sW_base + (uint32_t)(((bufi * KC + frow) * (2 * FT)) * 4);
        CPA16(wd + fcw * 16,      wr + fcw * 4);
        CPA16(wd + fcw * 16 + 16, wr + fcw * 4 + 4);
        const float* pr = gP + (size_t)(k0 + frow) * LPAD;
        uint32_t pd = sP_base + (uint32_t)(((bufi * KC + frow) * LT) * 4);
        CPA16(pd + fcp * 16, pr + fcp * 4);
        asm volatile("cp.async.commit_group;\n" ::: "memory");
    };

    const int tc = tid & 15;             // W chunk id -> f = {2tc,2tc+1,2tc+32,2tc+33}
    const int tl = (tid >> 4) * 4;       // 4 consecutive l

    unsigned long long acc[4][2];        // acc[fi][lpair]
#pragma unroll
    for (int i = 0; i < 4; i++) { acc[i][0] = 0ULL; acc[i][1] = 0ULL; }

    const unsigned long long ABSM = 0x7FFFFFFF7FFFFFFFULL;

    fill(0, 0);
    fill(1, 1);
    int buf = 0;
    for (int s = 0; s < NKC; s++) {
        asm volatile("cp.async.wait_group 1;\n" ::: "memory");
        __syncthreads();
        if (s + 2 < NKC) {
            int nbuf = buf + 2; if (nbuf >= NST) nbuf -= NST;
            fill(s + 2, nbuf);
        }
#pragma unroll
        for (int kc = 0; kc < KC; kc++) {
            ulonglong2 wA = *reinterpret_cast<const ulonglong2*>(&sWd[buf][kc][4 * tc]);       // (w0,w0),(w1,w1)
            ulonglong2 wB = *reinterpret_cast<const ulonglong2*>(&sWd[buf][kc][4 * tc + 64]);  // (w2,w2),(w3,w3)
            ulonglong2 pv = *reinterpret_cast<const ulonglong2*>(&sP[buf][kc][tl]);            // (p0,p1),(p2,p3)
            unsigned long long w[4] = {wA.x, wA.y, wB.x, wB.y};
#pragma unroll
            for (int i = 0; i < 4; i++) {
                unsigned long long d0 = add2(w[i], pv.x) & ABSM;   // |w - p| packed over l
                unsigned long long d1 = add2(w[i], pv.y) & ABSM;
                acc[i][0] = add2(acc[i][0], d0);
                acc[i][1] = add2(acc[i][1], d1);
            }
        }
        buf = buf + 1 == NST ? 0 : buf + 1;
    }

    // epilogue: out = -sum
    const int lbase = l0 + tl;
    if (lbase < LL) {   // LL % 4 == 0 -> whole float4 valid or invalid
        const int fl[4] = {2 * tc, 2 * tc + 1, 2 * tc + 32, 2 * tc + 33};
#pragma unroll
        for (int i = 0; i < 4; i++) {
            float a0, a1, a2, a3;
            unpack2(acc[i][0], a0, a1);
            unpack2(acc[i][1], a2, a3);
            float4 v = make_float4(-a0, -a1, -a2, -a3);
            *reinterpret_cast<float4*>(&out[((size_t)(b * FF + f0 + fl[i])) * LL + lbase]) = v;
        }
    }
}

extern "C" void kernel_launch(void* const* d_in, const int* in_sizes, int n_in,
                              void* d_out, int out_size) {
    const float* x  = (const float*)d_in[0];   // [16,128,28,28]
    const float* Wg = (const float*)d_in[1];   // [128,128,3,3]
    float* out = (float*)d_out;                // [16,128,28,28]

    dim3 g1(13, 72, 16);
    dim3 b1(16, 16, 1);
    im2col_kernel<<<g1, b1>>>(x);
    wtrans_kernel<<<(FF * KK + 255) / 256, 256>>>(Wg);

    dim3 grid(LPAD / LT /*13*/, FF / FT /*2*/, BB /*16*/);
    adder_kernel<<<grid, 256>>>(out);
}